// round 2
// baseline (speedup 1.0000x reference)
#include <cuda_runtime.h>
#include <math.h>

#define M_TOK   8192     // B*S = 8*1024
#define DD      256      // hidden dim
#define KDIM    512      // combined input dim
#define VDIM    512      // virtual output dim (tau/forcing interleaved)
#define NLAYERS 4
#define TMAX    50

// ---- device scratch (allocation-free: static __device__ arrays) ----
__device__ float g_states[2][NLAYERS][M_TOK * DD];   // 64 MB ping-pong
__device__ float g_Wp[NLAYERS * KDIM * VDIM];        // packed weights, 4 MB
__device__ float g_bp[NLAYERS * VDIM];               // packed biases
__device__ int      g_done;
__device__ int      g_result;
__device__ unsigned g_delta;   // float bits (nonneg), atomicMax-able
__device__ int      g_last;    // parity of buffer holding final states

// ---------------------------------------------------------------
__global__ void init_kernel() {
    size_t idx = (size_t)blockIdx.x * blockDim.x + threadIdx.x;
    size_t n4  = (size_t)NLAYERS * M_TOK * DD / 4;   // zero buffer 0 only
    if (idx < n4) ((float4*)&g_states[0][0][0])[idx] = make_float4(0.f, 0.f, 0.f, 0.f);
    if (idx == 0) { g_done = 0; g_result = TMAX; g_delta = 0u; g_last = 0; }
}

// Pack Wbig: virtual column v -> (d = v>>1, half = v&1).
// half==0 row = Wt[d][k] (tau); half==1 row = [Wi[d] | Ws[d]] (forcing).
__global__ void pack_kernel(const float* __restrict__ Ws, const float* __restrict__ bs,
                            const float* __restrict__ Wi, const float* __restrict__ bi,
                            const float* __restrict__ Wt, const float* __restrict__ bt) {
    int idx = blockIdx.x * blockDim.x + threadIdx.x;
    int total = NLAYERS * KDIM * VDIM;
    if (idx < total) {
        int l = idx / (KDIM * VDIM);
        int rem = idx % (KDIM * VDIM);
        int k = rem / VDIM;
        int v = rem % VDIM;
        int d = v >> 1, half = v & 1;
        float w;
        if (half == 0)      w = Wt[(l * DD + d) * KDIM + k];
        else if (k < DD)    w = Wi[(l * DD + d) * DD + k];
        else                w = Ws[(l * DD + d) * DD + (k - DD)];
        g_Wp[idx] = w;
    }
    if (idx < NLAYERS * VDIM) {
        int l = idx / VDIM, v = idx % VDIM, d = v >> 1, half = v & 1;
        g_bp[idx] = half ? (bs[l * DD + d] + bi[l * DD + d]) : bt[l * DD + d];
    }
}

// One layer-step: fused GEMM [8192x512]x[512x512]^T + epilogue + delta reduce.
// Tile: 128 tokens x 64 virtual cols, 256 threads, 8x4 acc per thread.
__global__ __launch_bounds__(256, 2)
void layer_kernel(const float* __restrict__ x, int l, int rb) {
    if (g_done) return;                               // frozen after convergence
    const float* __restrict__ curin = (l == 0) ? x : g_states[rb ^ 1][l - 1];
    const float* __restrict__ hprev = g_states[rb][l];
    float* __restrict__ hout        = g_states[rb ^ 1][l];
    const float* __restrict__ Wp    = &g_Wp[l * KDIM * VDIM];

    __shared__ float As[16][128];
    __shared__ float Bs[16][64];
    __shared__ float red[8];

    int tid = threadIdx.x;
    int ty = tid >> 4, tx = tid & 15;
    int m0 = blockIdx.x * 128;
    int v0 = blockIdx.y * 64;

    float acc[8][4];
#pragma unroll
    for (int i = 0; i < 8; i++)
#pragma unroll
        for (int j = 0; j < 4; j++) acc[i][j] = 0.f;

    for (int k0 = 0; k0 < KDIM; k0 += 16) {
        const float* Asrc = (k0 < DD) ? curin : hprev;   // combined = [cur ; h]
        int kb = k0 & (DD - 1);
#pragma unroll
        for (int s = 0; s < 2; s++) {                    // A tile 128x16, transposed store
            int slot = tid * 2 + s;                      // 0..511
            int ml = slot >> 2, k4 = slot & 3;
            float4 va = *(const float4*)&Asrc[(m0 + ml) * DD + kb + k4 * 4];
            As[k4 * 4 + 0][ml] = va.x; As[k4 * 4 + 1][ml] = va.y;
            As[k4 * 4 + 2][ml] = va.z; As[k4 * 4 + 3][ml] = va.w;
        }
        {                                                // B tile 16x64
            int kk = tid >> 4, v4 = tid & 15;
            *(float4*)&Bs[kk][v4 * 4] =
                *(const float4*)&Wp[(k0 + kk) * VDIM + v0 + v4 * 4];
        }
        __syncthreads();
#pragma unroll
        for (int kk = 0; kk < 16; kk++) {
            float4 a0 = *(const float4*)&As[kk][ty * 8];
            float4 a1 = *(const float4*)&As[kk][ty * 8 + 4];
            float4 bb = *(const float4*)&Bs[kk][tx * 4];
            float a[8] = {a0.x, a0.y, a0.z, a0.w, a1.x, a1.y, a1.z, a1.w};
            float b[4] = {bb.x, bb.y, bb.z, bb.w};
#pragma unroll
            for (int i = 0; i < 8; i++)
#pragma unroll
                for (int j = 0; j < 4; j++) acc[i][j] += a[i] * b[j];
        }
        __syncthreads();
    }

    // Epilogue: thread's 4 virtual cols = {tau(d0), forc(d0), tau(d0+1), forc(d0+1)}
    float bT0 = g_bp[l * VDIM + v0 + tx * 4 + 0];
    float bF0 = g_bp[l * VDIM + v0 + tx * 4 + 1];
    float bT1 = g_bp[l * VDIM + v0 + tx * 4 + 2];
    float bF1 = g_bp[l * VDIM + v0 + tx * 4 + 3];
    int d0 = (v0 >> 1) + tx * 2;
    float dmax = 0.f;
#pragma unroll
    for (int i = 0; i < 8; i++) {
        int m = m0 + ty * 8 + i;
        {
            float tau  = 1.f / (1.f + expf(-(acc[i][0] + bT0)));
            float forc = tanhf(acc[i][1] + bF0);
            float h = hprev[m * DD + d0];
            float hn = h + 0.05f * (forc - h / (tau + 1e-6f));
            hn = fminf(10.f, fmaxf(-10.f, hn));
            dmax = fmaxf(dmax, fabsf(hn - h));
            hout[m * DD + d0] = hn;
        }
        {
            float tau  = 1.f / (1.f + expf(-(acc[i][2] + bT1)));
            float forc = tanhf(acc[i][3] + bF1);
            float h = hprev[m * DD + d0 + 1];
            float hn = h + 0.05f * (forc - h / (tau + 1e-6f));
            hn = fminf(10.f, fmaxf(-10.f, hn));
            dmax = fmaxf(dmax, fabsf(hn - h));
            hout[m * DD + d0 + 1] = hn;
        }
    }
    // block-reduce max delta, one atomic per block
#pragma unroll
    for (int o = 16; o; o >>= 1) dmax = fmaxf(dmax, __shfl_xor_sync(0xffffffffu, dmax, o));
    if ((tid & 31) == 0) red[tid >> 5] = dmax;
    __syncthreads();
    if (tid == 0) {
        float v = red[0];
#pragma unroll
        for (int w = 1; w < 8; w++) v = fmaxf(v, red[w]);
        atomicMax(&g_delta, __float_as_uint(v));
    }
}

__global__ void check_kernel(int t) {
    if (!g_done) {
        g_last = (t & 1) ^ 1;                      // buffer written this step
        if (__uint_as_float(g_delta) < 1e-3f) { g_done = 1; g_result = t; }
    }
    g_delta = 0u;
}

__global__ void output_kernel(float* __restrict__ out, int n) {
    int idx = blockIdx.x * blockDim.x + threadIdx.x;
    if (idx >= n) return;
    if (idx < M_TOK * DD) out[idx] = g_states[g_last][NLAYERS - 1][idx];
    else                  out[idx] = (float)g_result;   // convergence step index
}

// ---------------------------------------------------------------
extern "C" void kernel_launch(void* const* d_in, const int* in_sizes, int n_in,
                              void* d_out, int out_size) {
    const float* x  = (const float*)d_in[0];
    const float* Ws = (const float*)d_in[1];
    const float* bs = (const float*)d_in[2];
    const float* Wi = (const float*)d_in[3];
    const float* bi = (const float*)d_in[4];
    const float* Wt = (const float*)d_in[5];
    const float* bt = (const float*)d_in[6];

    init_kernel<<<8192, 256>>>();
    pack_kernel<<<(NLAYERS * KDIM * VDIM + 255) / 256, 256>>>(Ws, bs, Wi, bi, Wt, bt);

    dim3 grid(M_TOK / 128, VDIM / 64);   // 64 x 8 = 512 blocks
    for (int t = 0; t < TMAX; t++) {
        for (int l = 0; l < NLAYERS; l++)
            layer_kernel<<<grid, 256>>>(x, l, t & 1);
        check_kernel<<<1, 1>>>(t);
    }
    output_kernel<<<(out_size + 255) / 256, 256>>>((float*)d_out, out_size);
}

// round 5
// speedup vs baseline: 2.4436x; 2.4436x over previous
#include <cuda_runtime.h>
#include <cuda_bf16.h>
#include <math.h>
#include <stdint.h>

#define M_TOK   8192     // B*S
#define DD      256      // hidden dim
#define KDIM    512      // combined input dim
#define VDIM    512      // virtual output dim (tau/forcing interleaved)
#define NLAYERS 4
#define TMAX    50

#define MT 128           // M tile per CTA
#define NT 256           // N tile per CTA (TMEM D cols)
#define KB 64            // K per stage (64 bf16 = 128B rows, SW128 atom)
#define STAGE_BYTES 98304    // Ahi 16K + Alo 16K + Bhi 32K + Blo 32K
#define DYN_SMEM (2*STAGE_BYTES + 1024)   // +1024 for manual alignment

// idesc kind::f16: dtype=F32, atype=btype=BF16, N=256, M=128
#define IDESC 0x8400490u

// Arch-specific gate: tcgen05 only exists in the sm_103a pass. The harness
// also compiles a baseline compute_103 pass where these instructions are
// illegal — that pass gets a correct fp32 FFMA fallback instead.
#if defined(__CUDA_ARCH__) && (__CUDA_ARCH__ == 1030) && \
    (defined(__CUDA_ARCH_FEAT_SM103_ALL) || defined(__CUDA_ARCH_SPECIFIC__))
#define TC_PATH 1
#else
#define TC_PATH 0
#endif

// ---------------- device globals (allocation-free scratch) ----------------
__device__ __align__(256) float          g_s32[2][NLAYERS][M_TOK*DD];  // fp32 states
__device__ __align__(256) __nv_bfloat16  g_sbh[2][NLAYERS][M_TOK*DD];  // bf16 hi plane
__device__ __align__(256) __nv_bfloat16  g_sbl[2][NLAYERS][M_TOK*DD];  // bf16 lo plane
__device__ __align__(256) float          g_x32[M_TOK*DD];
__device__ __align__(256) __nv_bfloat16  g_xh[M_TOK*DD];
__device__ __align__(256) __nv_bfloat16  g_xl[M_TOK*DD];
__device__ __align__(256) __nv_bfloat16  g_wh[NLAYERS*VDIM*KDIM];      // [l][v][k] K-major
__device__ __align__(256) __nv_bfloat16  g_wl[NLAYERS*VDIM*KDIM];
__device__ __align__(256) float          g_Wp[NLAYERS*KDIM*VDIM];      // [l][k][v] fp32 (fallback)
__device__ float    g_bp[NLAYERS*VDIM];
__device__ int      g_done;
__device__ int      g_result;
__device__ unsigned g_delta;
__device__ int      g_last;

// ---------------- inline PTX helpers ----------------
__device__ __forceinline__ uint32_t smem_u32(const void* p) {
    uint32_t a;
    asm("{ .reg .u64 t; cvta.to.shared.u64 t, %1; cvt.u32.u64 %0, t; }" : "=r"(a) : "l"(p));
    return a;
}
__device__ __forceinline__ uint32_t elect_one() {
    uint32_t p;
    asm volatile("{\n\t.reg .pred p;\n\telect.sync _|p, 0xFFFFFFFF;\n\tselp.b32 %0, 1, 0, p;\n\t}" : "=r"(p));
    return p;
}
#define SWZ(o) ((o) ^ (((o) >> 3) & 0x70))

__device__ __forceinline__ uint64_t make_desc(uint32_t addr) {
    const uint64_t base = (2ULL << 61) | (1ULL << 46) | (64ULL << 32) | (1ULL << 16); // SW128, LBO=1, SBO=64
    return base | (uint64_t)((addr >> 4) & 0x3FFF);
}

#define MBAR_INIT(a, c) asm volatile("mbarrier.init.shared.b64 [%0], %1;" :: "r"(a), "r"(c) : "memory")
#define MBAR_WAIT(a, par) do { \
    uint32_t _m = (a), _p = (par), _d; \
    asm volatile("{\n\t.reg .pred p;\n\tmbarrier.try_wait.parity.acquire.cta.shared::cta.b64 p, [%1], %2;\n\tselp.b32 %0, 1, 0, p;\n\t}" \
        : "=r"(_d) : "r"(_m), "r"(_p) : "memory"); \
    if (!_d) { \
        asm volatile("{\n\t.reg .pred P1;\n\tWL_%=:\n\tmbarrier.try_wait.parity.acquire.cta.shared::cta.b64 P1, [%0], %1, 0x989680;\n\t@P1 bra.uni WD_%=;\n\tbra.uni WL_%=;\n\tWD_%=:\n\t}" \
            :: "r"(_m), "r"(_p) : "memory"); \
    } } while (0)

#define CP16(dst, src) asm volatile("cp.async.cg.shared.global [%0], [%1], 16;" :: "r"(dst), "l"(src) : "memory")
#define CP_COMMIT()    asm volatile("cp.async.commit_group;" ::: "memory")
#define CP_WAIT0()     asm volatile("cp.async.wait_group 0;" ::: "memory")
#define FENCE_ASYNC()  asm volatile("fence.proxy.async.shared::cta;" ::: "memory")

#if TC_PATH
#define TM_ALLOC(sa, n)   asm volatile("tcgen05.alloc.cta_group::1.sync.aligned.shared::cta.b32 [%0], %1;" :: "r"(sa), "r"(n) : "memory")
#define TM_DEALLOC(t, n)  asm volatile("tcgen05.dealloc.cta_group::1.sync.aligned.b32 %0, %1;" :: "r"(t), "r"(n))
#define TM_RELINQ()       asm volatile("tcgen05.relinquish_alloc_permit.cta_group::1.sync.aligned;")
#define TM_COMMIT(mb)     asm volatile("tcgen05.commit.cta_group::1.mbarrier::arrive::one.shared::cluster.b64 [%0];" :: "r"(mb) : "memory")
#define TM_WAIT_LD()      asm volatile("tcgen05.wait::ld.sync.aligned;" ::: "memory")
#define TM_FENCE_AFTER()  asm volatile("tcgen05.fence::after_thread_sync;" ::: "memory")
#define TM_FENCE_BEFORE() asm volatile("tcgen05.fence::before_thread_sync;" ::: "memory")

__device__ __forceinline__ void mma_f16_ss(uint32_t d, uint64_t a, uint64_t b, uint32_t idesc, bool en) {
    uint32_t e = en ? 1u : 0u;
    asm volatile(
        "{\n\t.reg .pred p;\n\tsetp.ne.u32 p, %5, 0;\n\t"
        "tcgen05.mma.cta_group::1.kind::f16 [%0], %1, %2, %3, {%4, %4, %4, %4}, p;\n\t}"
        :: "r"(d), "l"(a), "l"(b), "r"(idesc), "r"(0u), "r"(e) : "memory");
}

#define TM_LD_X32(r, ta) \
    asm volatile("tcgen05.ld.sync.aligned.32x32b.x32.b32 " \
        "{%0,%1,%2,%3,%4,%5,%6,%7,%8,%9,%10,%11,%12,%13,%14,%15," \
        "%16,%17,%18,%19,%20,%21,%22,%23,%24,%25,%26,%27,%28,%29,%30,%31}, [%32];" \
        : "=r"((r)[0]),"=r"((r)[1]),"=r"((r)[2]),"=r"((r)[3]),"=r"((r)[4]),"=r"((r)[5]),"=r"((r)[6]),"=r"((r)[7]), \
          "=r"((r)[8]),"=r"((r)[9]),"=r"((r)[10]),"=r"((r)[11]),"=r"((r)[12]),"=r"((r)[13]),"=r"((r)[14]),"=r"((r)[15]), \
          "=r"((r)[16]),"=r"((r)[17]),"=r"((r)[18]),"=r"((r)[19]),"=r"((r)[20]),"=r"((r)[21]),"=r"((r)[22]),"=r"((r)[23]), \
          "=r"((r)[24]),"=r"((r)[25]),"=r"((r)[26]),"=r"((r)[27]),"=r"((r)[28]),"=r"((r)[29]),"=r"((r)[30]),"=r"((r)[31]) \
        : "r"(ta))
#endif // TC_PATH

// ---------------------------------------------------------------
__global__ void init_kernel() {
    size_t idx = (size_t)blockIdx.x * blockDim.x + threadIdx.x;
    float4 z = make_float4(0.f, 0.f, 0.f, 0.f);
    if (idx < (size_t)NLAYERS * M_TOK * DD / 4) ((float4*)&g_s32[0][0][0])[idx] = z;
    if (idx < (size_t)NLAYERS * M_TOK * DD / 8) {
        ((float4*)&g_sbh[0][0][0])[idx] = z;
        ((float4*)&g_sbl[0][0][0])[idx] = z;
    }
    if (idx == 0) { g_done = 0; g_result = TMAX; g_delta = 0u; g_last = 0; }
}

__global__ void xcvt_kernel(const float* __restrict__ x) {
    int idx = blockIdx.x * blockDim.x + threadIdx.x;
    if (idx < M_TOK * DD) {
        float v = x[idx];
        g_x32[idx] = v;
        __nv_bfloat16 hi = __float2bfloat16(v);
        g_xh[idx] = hi;
        g_xl[idx] = __float2bfloat16(v - __bfloat162float(hi));
    }
}

__global__ void pack_kernel(const float* __restrict__ Ws, const float* __restrict__ bs,
                            const float* __restrict__ Wi, const float* __restrict__ bi,
                            const float* __restrict__ Wt, const float* __restrict__ bt) {
    int idx = blockIdx.x * blockDim.x + threadIdx.x;
    int total = NLAYERS * KDIM * VDIM;
    if (idx < total) {
        int l = idx / (KDIM * VDIM);
        int rem = idx % (KDIM * VDIM);
        int k = rem / VDIM;
        int v = rem % VDIM;
        int d = v >> 1, half = v & 1;
        float w;
        if (half == 0)      w = Wt[(l * DD + d) * KDIM + k];
        else if (k < DD)    w = Wi[(l * DD + d) * DD + k];
        else                w = Ws[(l * DD + d) * DD + (k - DD)];
        g_Wp[idx] = w;                                    // [l][k][v] fp32 (fallback path)
        size_t o = ((size_t)(l * VDIM + v)) * KDIM + k;   // [l][v][k] bf16 K-major (tensor path)
        __nv_bfloat16 hi = __float2bfloat16(w);
        g_wh[o] = hi;
        g_wl[o] = __float2bfloat16(w - __bfloat162float(hi));
    }
    if (idx < NLAYERS * VDIM) {
        int l = idx / VDIM, v = idx % VDIM, d = v >> 1, half = v & 1;
        g_bp[idx] = half ? (bs[l * DD + d] + bi[l * DD + d]) : bt[l * DD + d];
    }
}

// epilogue scalar, shared by both paths
__device__ __forceinline__ float epi_update(float pt, float pf, float h, float& dmax) {
    float tau  = 1.f / (1.f + expf(-pt));
    float forc = tanhf(pf);
    float hn = h + 0.05f * (forc - h / (tau + 1e-6f));
    hn = fminf(10.f, fmaxf(-10.f, hn));
    dmax = fmaxf(dmax, fabsf(hn - h));
    return hn;
}

// One layer-step: GEMM [8192x512]x[512x512]^T + fused epilogue + delta reduce.
__global__ __launch_bounds__(256, 1)
void layer_kernel(int l, int rb) {
    if (g_done) return;

    extern __shared__ char dynsmem[];
    const int tid = threadIdx.x;

#if TC_PATH
    // ================= tcgen05 split-bf16 path =================
    __shared__ uint32_t s_tmem;
    __shared__ __align__(8) uint64_t s_mbar[2];
    __shared__ float s_red[4];

    const int wid = tid >> 5, lane = tid & 31;
    const int m0 = blockIdx.x * MT;
    const int v0 = blockIdx.y * NT;

    const __nv_bfloat16* __restrict__ cin_h = (l == 0) ? g_xh : g_sbh[rb ^ 1][l - 1];
    const __nv_bfloat16* __restrict__ cin_l = (l == 0) ? g_xl : g_sbl[rb ^ 1][l - 1];
    const __nv_bfloat16* __restrict__ hp_h  = g_sbh[rb][l];
    const __nv_bfloat16* __restrict__ hp_l  = g_sbl[rb][l];
    const float* __restrict__ hp32          = g_s32[rb][l];
    float* __restrict__ o32                 = g_s32[rb ^ 1][l];
    __nv_bfloat16* __restrict__ obh         = g_sbh[rb ^ 1][l];
    __nv_bfloat16* __restrict__ obl         = g_sbl[rb ^ 1][l];
    const __nv_bfloat16* __restrict__ wbh   = g_wh + (size_t)l * VDIM * KDIM;
    const __nv_bfloat16* __restrict__ wbl   = g_wl + (size_t)l * VDIM * KDIM;

    const uint32_t mbar0 = smem_u32(&s_mbar[0]);
    const uint32_t mbar1 = smem_u32(&s_mbar[1]);
    if (tid == 0) { MBAR_INIT(mbar0, 1); MBAR_INIT(mbar1, 1); }
    if (wid == 0) TM_ALLOC(smem_u32(&s_tmem), NT);
    __syncthreads();
    uint32_t tmem;
    asm volatile("ld.shared.b32 %0, [%1];" : "=r"(tmem) : "r"(smem_u32(&s_tmem)));

    // SW128 tiles require a 1024-byte-aligned base: dynamic smem only
    // guarantees 16B, and the static __shared__ vars shift it. Round up.
    const uint32_t sbase = (smem_u32(dynsmem) + 1023u) & ~1023u;

    // -------- pipelined K loop: 8 blocks of K=64, 2 smem stages --------
    for (int kb = 0; kb < 8; kb++) {
        const int s = kb & 1;
        const uint32_t stage = sbase + s * STAGE_BYTES;
        const uint32_t mbar_s = s ? mbar1 : mbar0;
        if (kb >= 2) MBAR_WAIT(mbar_s, ((kb >> 1) - 1) & 1);

        const __nv_bfloat16* ah;
        const __nv_bfloat16* al;
        int acol;
        if (kb < 4) { ah = cin_h; al = cin_l; acol = kb * KB; }
        else        { ah = hp_h;  al = hp_l;  acol = (kb - 4) * KB; }

        // A tiles: 128 rows x 64 bf16 (hi, lo), SW128
        for (int i = tid; i < 2048; i += 256) {
            int plane = i >> 10, rid = (i >> 3) & 127, c = i & 7;
            const __nv_bfloat16* src = (plane ? al : ah) + (size_t)(m0 + rid) * DD + acol + c * 8;
            uint32_t dst = stage + plane * 16384 + SWZ(rid * 128 + c * 16);
            CP16(dst, src);
        }
        // B tiles: 256 rows (v) x 64 bf16 (hi, lo), SW128
        for (int i = tid; i < 4096; i += 256) {
            int plane = i >> 11, rid = (i >> 3) & 255, c = i & 7;
            const __nv_bfloat16* src = (plane ? wbl : wbh) + (size_t)(v0 + rid) * KDIM + kb * KB + c * 8;
            uint32_t dst = stage + 32768 + plane * 32768 + SWZ(rid * 128 + c * 16);
            CP16(dst, src);
        }
        CP_COMMIT();
        CP_WAIT0();
        FENCE_ASYNC();
        __syncthreads();

        if (wid == 0 && elect_one()) {
            uint64_t dah = make_desc(stage);
            uint64_t dal = make_desc(stage + 16384);
            uint64_t dbh = make_desc(stage + 32768);
            uint64_t dbl = make_desc(stage + 65536);
#pragma unroll
            for (int pass = 0; pass < 3; pass++) {
                uint64_t da = (pass == 2) ? dal : dah;
                uint64_t db = (pass == 1) ? dbl : dbh;
#pragma unroll
                for (int kc = 0; kc < 4; kc++)
                    mma_f16_ss(tmem, da + kc * 2, db + kc * 2, IDESC,
                               !(kb == 0 && pass == 0 && kc == 0));
            }
            TM_COMMIT(mbar_s);
        }
    }

    // final commit was at kb=7 on mbar1 (4th use) -> completion parity 1
    MBAR_WAIT(mbar1, 1);
    TM_FENCE_AFTER();

    // -------- fused epilogue: warps 0-3 read TMEM, 32 cols at a time --------
    float dmax = 0.f;
    if (tid < 128) {
        const int m = m0 + wid * 32 + lane;
        const float* hp = hp32 + (size_t)m * DD;
        float* orow = o32 + (size_t)m * DD;
        __nv_bfloat16* ohr = obh + (size_t)m * DD;
        __nv_bfloat16* olr = obl + (size_t)m * DD;
#pragma unroll
        for (int cb = 0; cb < 8; cb++) {
            uint32_t r[32];
            TM_LD_X32(r, tmem + cb * 32);
            TM_WAIT_LD();
            int dbase = (v0 >> 1) + cb * 16;
            const float* bp = &g_bp[l * VDIM + v0 + cb * 32];
#pragma unroll
            for (int j = 0; j < 16; j++) {
                float pt = __uint_as_float(r[2 * j])     + bp[2 * j];
                float pf = __uint_as_float(r[2 * j + 1]) + bp[2 * j + 1];
                float hn = epi_update(pt, pf, hp[dbase + j], dmax);
                orow[dbase + j] = hn;
                __nv_bfloat16 hi = __float2bfloat16(hn);
                ohr[dbase + j] = hi;
                olr[dbase + j] = __float2bfloat16(hn - __bfloat162float(hi));
            }
        }
        TM_FENCE_BEFORE();
#pragma unroll
        for (int o = 16; o; o >>= 1) dmax = fmaxf(dmax, __shfl_xor_sync(0xffffffffu, dmax, o));
        if (lane == 0) s_red[wid] = dmax;
    }
    __syncthreads();
    if (tid == 0) {
        float v = fmaxf(fmaxf(s_red[0], s_red[1]), fmaxf(s_red[2], s_red[3]));
        atomicMax(&g_delta, __float_as_uint(v));
    }
    __syncthreads();
    if (wid == 0) { TM_RELINQ(); TM_DEALLOC(tmem, NT); }

#else
    // ================= fp32 FFMA fallback (baseline compile pass) =================
    float* As = (float*)dynsmem;              // [16][128]
    float* Bs = (float*)(dynsmem + 16 * 128 * 4); // [16][64]
    __shared__ float red[8];

    const float* __restrict__ curin = (l == 0) ? g_x32 : g_s32[rb ^ 1][l - 1];
    const float* __restrict__ hprev = g_s32[rb][l];
    float* __restrict__ hout        = g_s32[rb ^ 1][l];
    __nv_bfloat16* __restrict__ obh = g_sbh[rb ^ 1][l];
    __nv_bfloat16* __restrict__ obl = g_sbl[rb ^ 1][l];
    const float* __restrict__ Wp    = &g_Wp[l * KDIM * VDIM];

    int ty = tid >> 4, tx = tid & 15;
    int m0 = blockIdx.x * 128;
    float dmax_all = 0.f;

    for (int vc = 0; vc < 4; vc++) {
        int v0 = blockIdx.y * NT + vc * 64;
        float acc[8][4];
#pragma unroll
        for (int i = 0; i < 8; i++)
#pragma unroll
            for (int j = 0; j < 4; j++) acc[i][j] = 0.f;

        for (int k0 = 0; k0 < KDIM; k0 += 16) {
            const float* Asrc = (k0 < DD) ? curin : hprev;
            int kb2 = k0 & (DD - 1);
            __syncthreads();
#pragma unroll
            for (int s = 0; s < 2; s++) {
                int slot = tid * 2 + s;
                int ml = slot >> 2, k4 = slot & 3;
                float4 va = *(const float4*)&Asrc[(size_t)(m0 + ml) * DD + kb2 + k4 * 4];
                As[(k4 * 4 + 0) * 128 + ml] = va.x; As[(k4 * 4 + 1) * 128 + ml] = va.y;
                As[(k4 * 4 + 2) * 128 + ml] = va.z; As[(k4 * 4 + 3) * 128 + ml] = va.w;
            }
            {
                int kk = tid >> 4, v4 = tid & 15;
                *(float4*)&Bs[kk * 64 + v4 * 4] =
                    *(const float4*)&Wp[(size_t)(k0 + kk) * VDIM + v0 + v4 * 4];
            }
            __syncthreads();
#pragma unroll
            for (int kk = 0; kk < 16; kk++) {
                float4 a0 = *(const float4*)&As[kk * 128 + ty * 8];
                float4 a1 = *(const float4*)&As[kk * 128 + ty * 8 + 4];
                float4 bb = *(const float4*)&Bs[kk * 64 + tx * 4];
                float a[8] = {a0.x, a0.y, a0.z, a0.w, a1.x, a1.y, a1.z, a1.w};
                float b[4] = {bb.x, bb.y, bb.z, bb.w};
#pragma unroll
                for (int i = 0; i < 8; i++)
#pragma unroll
                    for (int j = 0; j < 4; j++) acc[i][j] += a[i] * b[j];
            }
        }

        float bT0 = g_bp[l * VDIM + v0 + tx * 4 + 0];
        float bF0 = g_bp[l * VDIM + v0 + tx * 4 + 1];
        float bT1 = g_bp[l * VDIM + v0 + tx * 4 + 2];
        float bF1 = g_bp[l * VDIM + v0 + tx * 4 + 3];
        int d0 = (v0 >> 1) + tx * 2;
#pragma unroll
        for (int i = 0; i < 8; i++) {
            int m = m0 + ty * 8 + i;
#pragma unroll
            for (int q = 0; q < 2; q++) {
                float hn = epi_update(acc[i][2 * q] + (q ? bT1 : bT0),
                                      acc[i][2 * q + 1] + (q ? bF1 : bF0),
                                      hprev[(size_t)m * DD + d0 + q], dmax_all);
                hout[(size_t)m * DD + d0 + q] = hn;
                __nv_bfloat16 hi = __float2bfloat16(hn);
                obh[(size_t)m * DD + d0 + q] = hi;
                obl[(size_t)m * DD + d0 + q] = __float2bfloat16(hn - __bfloat162float(hi));
            }
        }
    }
#pragma unroll
    for (int o = 16; o; o >>= 1) dmax_all = fmaxf(dmax_all, __shfl_xor_sync(0xffffffffu, dmax_all, o));
    if ((tid & 31) == 0) red[tid >> 5] = dmax_all;
    __syncthreads();
    if (tid == 0) {
        float v = red[0];
#pragma unroll
        for (int w = 1; w < 8; w++) v = fmaxf(v, red[w]);
        atomicMax(&g_delta, __float_as_uint(v));
    }
#endif
}

__global__ void check_kernel(int t) {
    if (!g_done) {
        g_last = (t & 1) ^ 1;
        if (__uint_as_float(g_delta) < 1e-3f) { g_done = 1; g_result = t; }
    }
    g_delta = 0u;
}

__global__ void output_kernel(float* __restrict__ out, int n) {
    int idx = blockIdx.x * blockDim.x + threadIdx.x;
    if (idx >= n) return;
    if (idx < M_TOK * DD) out[idx] = g_s32[g_last][NLAYERS - 1][idx];
    else                  out[idx] = (float)g_result;
}

// ---------------------------------------------------------------
extern "C" void kernel_launch(void* const* d_in, const int* in_sizes, int n_in,
                              void* d_out, int out_size) {
    const float* x  = (const float*)d_in[0];
    const float* Ws = (const float*)d_in[1];
    const float* bs = (const float*)d_in[2];
    const float* Wi = (const float*)d_in[3];
    const float* bi = (const float*)d_in[4];
    const float* Wt = (const float*)d_in[5];
    const float* bt = (const float*)d_in[6];

    static int attr_set = 0;
    if (!attr_set) {
        cudaFuncSetAttribute(layer_kernel, cudaFuncAttributeMaxDynamicSharedMemorySize, DYN_SMEM);
        attr_set = 1;
    }

    init_kernel<<<8192, 256>>>();
    xcvt_kernel<<<(M_TOK * DD + 255) / 256, 256>>>(x);
    pack_kernel<<<(NLAYERS * KDIM * VDIM + 255) / 256, 256>>>(Ws, bs, Wi, bi, Wt, bt);

    dim3 grid(M_TOK / MT, VDIM / NT);   // 64 x 2 = 128 CTAs
    for (int t = 0; t < TMAX; t++) {
        for (int l = 0; l < NLAYERS; l++)
            layer_kernel<<<grid, 256, DYN_SMEM>>>(l, t & 1);
        check_kernel<<<1, 1>>>(t);
    }
    output_kernel<<<(out_size + 255) / 256, 256>>>((float*)d_out, out_size);
}

// round 7
// speedup vs baseline: 4.2455x; 1.7374x over previous
#include <cuda_runtime.h>
#include <cuda_bf16.h>
#include <math.h>
#include <stdint.h>

#define M_TOK   8192     // B*S
#define DD      256      // hidden dim
#define KDIM    512      // combined input dim
#define VDIM    512      // virtual output dim (tau/forcing interleaved)
#define NLAYERS 4
#define TMAX    50

#define MT 128           // M tile per CTA
#define NT 256           // N tile per CTA (TMEM D cols)
#define STAGE_BYTES 98304    // Ahi 16K + Alo 16K + Bhi 32K + Blo 32K
#define DYN_SMEM (2*STAGE_BYTES + 1024)   // +1024 for manual alignment

// idesc kind::f16: dtype=F32, atype=btype=BF16, N=256, M=128
#define IDESC 0x8400490u

// Arch gate: tcgen05 only in the sm_103a pass; baseline compute_103 pass
// gets the fp32 FFMA fallback.
#if defined(__CUDA_ARCH__) && (__CUDA_ARCH__ == 1030) && \
    (defined(__CUDA_ARCH_FEAT_SM103_ALL) || defined(__CUDA_ARCH_SPECIFIC__))
#define TC_PATH 1
#else
#define TC_PATH 0
#endif

// ---------------- device globals (allocation-free scratch) ----------------
// bf16 planes are stored PRE-SWIZZLED, k-blocked: elem (kb, m, c) at
// (kb*8192 + m)*64 + (c ^ ((m&7)<<3)) — a 16 KB contiguous block per
// (kb, 128-row tile), byte-identical to the SW128 smem tile image.
__device__ __align__(256) float          g_s32[2][NLAYERS][M_TOK*DD];  // fp32 states
__device__ __align__(256) __nv_bfloat16  g_sbh[2][NLAYERS][M_TOK*DD];  // bf16 hi plane (swizzled)
__device__ __align__(256) __nv_bfloat16  g_sbl[2][NLAYERS][M_TOK*DD];  // bf16 lo plane (swizzled)
__device__ __align__(256) float          g_x32[M_TOK*DD];
__device__ __align__(256) __nv_bfloat16  g_xh[M_TOK*DD];               // swizzled
__device__ __align__(256) __nv_bfloat16  g_xl[M_TOK*DD];               // swizzled
// weights: [l][vt(2)][kb(8)] blocks of 256x64 swizzled = 16384 elems each
__device__ __align__(256) __nv_bfloat16  g_wh[NLAYERS*VDIM*KDIM];
__device__ __align__(256) __nv_bfloat16  g_wl[NLAYERS*VDIM*KDIM];
__device__ __align__(256) float          g_Wp[NLAYERS*KDIM*VDIM];      // fp32 [l][k][v] (fallback)
__device__ float    g_bp[NLAYERS*VDIM];
__device__ int      g_done;
__device__ int      g_result;
__device__ unsigned g_delta;
__device__ int      g_last;

// ---------------- inline PTX helpers ----------------
__device__ __forceinline__ uint32_t smem_u32(const void* p) {
    uint32_t a;
    asm("{ .reg .u64 t; cvta.to.shared.u64 t, %1; cvt.u32.u64 %0, t; }" : "=r"(a) : "l"(p));
    return a;
}

__device__ __forceinline__ uint64_t make_desc(uint32_t addr) {
    const uint64_t base = (2ULL << 61) | (1ULL << 46) | (64ULL << 32) | (1ULL << 16); // SW128, LBO=1, SBO=64
    return base | (uint64_t)((addr >> 4) & 0x3FFF);
}

#define MBAR_INIT(a, c) asm volatile("mbarrier.init.shared.b64 [%0], %1;" :: "r"(a), "r"(c) : "memory")
#define MBAR_EXPECT_TX(a, b) asm volatile("mbarrier.arrive.expect_tx.shared.b64 _, [%0], %1;" :: "r"(a), "r"(b) : "memory")
#define MBAR_WAIT(a, par) do { \
    uint32_t _m = (a), _p = (par), _d; \
    asm volatile("{\n\t.reg .pred p;\n\tmbarrier.try_wait.parity.acquire.cta.shared::cta.b64 p, [%1], %2;\n\tselp.b32 %0, 1, 0, p;\n\t}" \
        : "=r"(_d) : "r"(_m), "r"(_p) : "memory"); \
    if (!_d) { \
        asm volatile("{\n\t.reg .pred P1;\n\tWL_%=:\n\tmbarrier.try_wait.parity.acquire.cta.shared::cta.b64 P1, [%0], %1, 0x989680;\n\t@P1 bra.uni WD_%=;\n\tbra.uni WL_%=;\n\tWD_%=:\n\t}" \
            :: "r"(_m), "r"(_p) : "memory"); \
    } } while (0)

#if TC_PATH
#define CP_BULK(dst, src, bytes, mbar) \
    asm volatile("cp.async.bulk.shared::cluster.global.mbarrier::complete_tx::bytes [%0], [%1], %2, [%3];" \
        :: "r"(dst), "l"(src), "r"(bytes), "r"(mbar) : "memory")

#define TM_ALLOC(sa, n)   asm volatile("tcgen05.alloc.cta_group::1.sync.aligned.shared::cta.b32 [%0], %1;" :: "r"(sa), "r"(n) : "memory")
#define TM_DEALLOC(t, n)  asm volatile("tcgen05.dealloc.cta_group::1.sync.aligned.b32 %0, %1;" :: "r"(t), "r"(n))
#define TM_RELINQ()       asm volatile("tcgen05.relinquish_alloc_permit.cta_group::1.sync.aligned;")
#define TM_COMMIT(mb)     asm volatile("tcgen05.commit.cta_group::1.mbarrier::arrive::one.shared::cluster.b64 [%0];" :: "r"(mb) : "memory")
#define TM_WAIT_LD()      asm volatile("tcgen05.wait::ld.sync.aligned;" ::: "memory")
#define TM_FENCE_AFTER()  asm volatile("tcgen05.fence::after_thread_sync;" ::: "memory")
#define TM_FENCE_BEFORE() asm volatile("tcgen05.fence::before_thread_sync;" ::: "memory")

__device__ __forceinline__ void mma_f16_ss(uint32_t d, uint64_t a, uint64_t b, uint32_t idesc, bool en) {
    uint32_t e = en ? 1u : 0u;
    asm volatile(
        "{\n\t.reg .pred p;\n\tsetp.ne.u32 p, %5, 0;\n\t"
        "tcgen05.mma.cta_group::1.kind::f16 [%0], %1, %2, %3, {%4, %4, %4, %4}, p;\n\t}"
        :: "r"(d), "l"(a), "l"(b), "r"(idesc), "r"(0u), "r"(e) : "memory");
}

#define TM_LD_X32(r, ta) \
    asm volatile("tcgen05.ld.sync.aligned.32x32b.x32.b32 " \
        "{%0,%1,%2,%3,%4,%5,%6,%7,%8,%9,%10,%11,%12,%13,%14,%15," \
        "%16,%17,%18,%19,%20,%21,%22,%23,%24,%25,%26,%27,%28,%29,%30,%31}, [%32];" \
        : "=r"((r)[0]),"=r"((r)[1]),"=r"((r)[2]),"=r"((r)[3]),"=r"((r)[4]),"=r"((r)[5]),"=r"((r)[6]),"=r"((r)[7]), \
          "=r"((r)[8]),"=r"((r)[9]),"=r"((r)[10]),"=r"((r)[11]),"=r"((r)[12]),"=r"((r)[13]),"=r"((r)[14]),"=r"((r)[15]), \
          "=r"((r)[16]),"=r"((r)[17]),"=r"((r)[18]),"=r"((r)[19]),"=r"((r)[20]),"=r"((r)[21]),"=r"((r)[22]),"=r"((r)[23]), \
          "=r"((r)[24]),"=r"((r)[25]),"=r"((r)[26]),"=r"((r)[27]),"=r"((r)[28]),"=r"((r)[29]),"=r"((r)[30]),"=r"((r)[31]) \
        : "r"(ta))
#endif // TC_PATH

// ---------------------------------------------------------------
__global__ void init_kernel() {
    size_t idx = (size_t)blockIdx.x * blockDim.x + threadIdx.x;
    float4 z = make_float4(0.f, 0.f, 0.f, 0.f);
    if (idx < (size_t)NLAYERS * M_TOK * DD / 4) ((float4*)&g_s32[0][0][0])[idx] = z;
    if (idx < (size_t)NLAYERS * M_TOK * DD / 8) {
        ((float4*)&g_sbh[0][0][0])[idx] = z;
        ((float4*)&g_sbl[0][0][0])[idx] = z;
    }
    if (idx == 0) { g_done = 0; g_result = TMAX; g_delta = 0u; g_last = 0; }
}

__global__ void xcvt_kernel(const float* __restrict__ x) {
    int idx = blockIdx.x * blockDim.x + threadIdx.x;
    if (idx < M_TOK * DD) {
        float v = x[idx];
        g_x32[idx] = v;
        int m = idx >> 8, d = idx & 255;
        int kb = d >> 6, c = d & 63;
        size_t o = ((size_t)kb * 8192 + m) * 64 + (c ^ ((m & 7) << 3));  // swizzled
        __nv_bfloat16 hi = __float2bfloat16(v);
        g_xh[o] = hi;
        g_xl[o] = __float2bfloat16(v - __bfloat162float(hi));
    }
}

__global__ void pack_kernel(const float* __restrict__ Ws, const float* __restrict__ bs,
                            const float* __restrict__ Wi, const float* __restrict__ bi,
                            const float* __restrict__ Wt, const float* __restrict__ bt) {
    int idx = blockIdx.x * blockDim.x + threadIdx.x;
    int total = NLAYERS * KDIM * VDIM;
    if (idx < total) {
        int l = idx / (KDIM * VDIM);
        int rem = idx % (KDIM * VDIM);
        int k = rem / VDIM;
        int v = rem % VDIM;
        int d = v >> 1, half = v & 1;
        float w;
        if (half == 0)      w = Wt[(l * DD + d) * KDIM + k];
        else if (k < DD)    w = Wi[(l * DD + d) * DD + k];
        else                w = Ws[(l * DD + d) * DD + (k - DD)];
        g_Wp[idx] = w;                                    // fp32 [l][k][v] (fallback)
        // bf16 swizzled blocks: [l][vt][kb] of 256x64
        int vt = v >> 8, vl = v & 255, kb = k >> 6, c = k & 63;
        size_t o = (size_t)(((l * 2 + vt) * 8 + kb)) * 16384 + vl * 64 + (c ^ ((vl & 7) << 3));
        __nv_bfloat16 hi = __float2bfloat16(w);
        g_wh[o] = hi;
        g_wl[o] = __float2bfloat16(w - __bfloat162float(hi));
    }
    if (idx < NLAYERS * VDIM) {
        int l = idx / VDIM, v = idx % VDIM, d = v >> 1, half = v & 1;
        g_bp[idx] = half ? (bs[l * DD + d] + bi[l * DD + d]) : bt[l * DD + d];
    }
}

// epilogue scalar, shared by both paths
__device__ __forceinline__ float epi_update(float pt, float pf, float h, float& dmax) {
    float tau  = 1.f / (1.f + expf(-pt));
    float forc = tanhf(pf);
    float hn = h + 0.05f * (forc - h / (tau + 1e-6f));
    hn = fminf(10.f, fmaxf(-10.f, hn));
    dmax = fmaxf(dmax, fabsf(hn - h));
    return hn;
}

// One layer-step: GEMM [8192x512]x[512x512]^T + fused epilogue + delta reduce.
__global__ __launch_bounds__(256, 1)
void layer_kernel(int l, int rb) {
    if (g_done) return;

    extern __shared__ char dynsmem[];
    const int tid = threadIdx.x;

#if TC_PATH
    // ================= tcgen05 split-bf16, bulk-copy pipelined =================
    __shared__ uint32_t s_tmem;
    __shared__ __align__(8) uint64_t s_mbar[4];   // full[2], mma[2]
    __shared__ float s_red[8];

    const int wid = tid >> 5, lane = tid & 31;
    const int m0 = blockIdx.x * MT;
    const int vt = blockIdx.y;           // 0 or 1
    const int v0 = vt * NT;

    const __nv_bfloat16* __restrict__ cin_h = (l == 0) ? g_xh : g_sbh[rb ^ 1][l - 1];
    const __nv_bfloat16* __restrict__ cin_l = (l == 0) ? g_xl : g_sbl[rb ^ 1][l - 1];
    const __nv_bfloat16* __restrict__ hp_h  = g_sbh[rb][l];
    const __nv_bfloat16* __restrict__ hp_l  = g_sbl[rb][l];
    const float* __restrict__ hp32          = g_s32[rb][l];
    float* __restrict__ o32                 = g_s32[rb ^ 1][l];
    __nv_bfloat16* __restrict__ obh         = g_sbh[rb ^ 1][l];
    __nv_bfloat16* __restrict__ obl         = g_sbl[rb ^ 1][l];
    const __nv_bfloat16* __restrict__ wbh   = g_wh + (size_t)((l * 2 + vt) * 8) * 16384;
    const __nv_bfloat16* __restrict__ wbl   = g_wl + (size_t)((l * 2 + vt) * 8) * 16384;

    uint32_t full_mb[2], mma_mb[2];
    full_mb[0] = smem_u32(&s_mbar[0]); full_mb[1] = smem_u32(&s_mbar[1]);
    mma_mb[0]  = smem_u32(&s_mbar[2]); mma_mb[1]  = smem_u32(&s_mbar[3]);
    if (tid == 0) {
        MBAR_INIT(full_mb[0], 1); MBAR_INIT(full_mb[1], 1);
        MBAR_INIT(mma_mb[0], 1);  MBAR_INIT(mma_mb[1], 1);
    }
    if (wid == 0) TM_ALLOC(smem_u32(&s_tmem), NT);
    __syncthreads();
    uint32_t tmem;
    asm volatile("ld.shared.b32 %0, [%1];" : "=r"(tmem) : "r"(smem_u32(&s_tmem)));

    const uint32_t sbase = (smem_u32(dynsmem) + 1023u) & ~1023u;   // SW128 needs 1024-align

    if (tid == 0) {
        // ---- single-thread orchestration: bulk loads + MMA pipeline ----
        auto issue_loads = [&](int kb, uint32_t stage, uint32_t fmb) {
            MBAR_EXPECT_TX(fmb, (uint32_t)STAGE_BYTES);
            const __nv_bfloat16* ah; const __nv_bfloat16* al; int akb;
            if (kb < 4) { ah = cin_h; al = cin_l; akb = kb; }
            else        { ah = hp_h;  al = hp_l;  akb = kb - 4; }
            const __nv_bfloat16* ah_p = ah + ((size_t)akb * 8192 + m0) * 64;
            const __nv_bfloat16* al_p = al + ((size_t)akb * 8192 + m0) * 64;
            CP_BULK(stage,          ah_p,            16384u, fmb);
            CP_BULK(stage + 16384,  al_p,            16384u, fmb);
            CP_BULK(stage + 32768,  wbh + kb * 16384, 32768u, fmb);
            CP_BULK(stage + 65536,  wbl + kb * 16384, 32768u, fmb);
        };

        issue_loads(0, sbase, full_mb[0]);
        issue_loads(1, sbase + STAGE_BYTES, full_mb[1]);

        for (int kb = 0; kb < 8; kb++) {
            const int s = kb & 1, ph = (kb >> 1) & 1;
            const uint32_t stage = sbase + s * STAGE_BYTES;
            MBAR_WAIT(full_mb[s], ph);

            uint64_t dah = make_desc(stage);
            uint64_t dal = make_desc(stage + 16384);
            uint64_t dbh = make_desc(stage + 32768);
            uint64_t dbl = make_desc(stage + 65536);
#pragma unroll
            for (int pass = 0; pass < 3; pass++) {
                uint64_t da = (pass == 2) ? dal : dah;
                uint64_t db = (pass == 1) ? dbl : dbh;
#pragma unroll
                for (int kc = 0; kc < 4; kc++)
                    mma_f16_ss(tmem, da + kc * 2, db + kc * 2, IDESC,
                               !(kb == 0 && pass == 0 && kc == 0));
            }
            TM_COMMIT(mma_mb[s]);

            if (kb < 6) {
                MBAR_WAIT(mma_mb[s], ph);          // stage s MMAs done -> smem reusable
                issue_loads(kb + 2, stage, full_mb[s]);
            }
        }
        MBAR_WAIT(mma_mb[1], 1);                   // final MMA (kb=7, phase 3) done
    }
    __syncthreads();
    TM_FENCE_AFTER();

    // -------- fused epilogue: 8 warps; warp w -> rows (w&3)*32, col-half w>>2 --------
    float dmax = 0.f;
    {
        const int m = m0 + (wid & 3) * 32 + lane;
        const int cb0 = (wid >> 2) * 4;
        const float* hp = hp32 + (size_t)m * DD;
        float* orow = o32 + (size_t)m * DD;
        const int sw = (m & 7) << 3;
#pragma unroll
        for (int ci = 0; ci < 4; ci++) {
            const int cb = cb0 + ci;
            uint32_t r[32];
            TM_LD_X32(r, tmem + cb * 32);
            TM_WAIT_LD();
            const int dbase = (v0 >> 1) + cb * 16;
            const float* bp = &g_bp[l * VDIM + v0 + cb * 32];
            __align__(16) float hnv[16];
            __align__(16) __nv_bfloat16 hib[16], lob[16];
#pragma unroll
            for (int j = 0; j < 16; j++) {
                float pt = __uint_as_float(r[2 * j])     + bp[2 * j];
                float pf = __uint_as_float(r[2 * j + 1]) + bp[2 * j + 1];
                float hn = epi_update(pt, pf, hp[dbase + j], dmax);
                hnv[j] = hn;
                __nv_bfloat16 hi = __float2bfloat16(hn);
                hib[j] = hi;
                lob[j] = __float2bfloat16(hn - __bfloat162float(hi));
            }
#pragma unroll
            for (int q = 0; q < 4; q++)
                *(float4*)&orow[dbase + q * 4] = *(float4*)&hnv[q * 4];
            // swizzled k-blocked plane stores (2x16B per plane)
            const int kbd = dbase >> 6, c0 = dbase & 63;
            const size_t eb = ((size_t)kbd * 8192 + m) * 64;
            *(uint4*)&obh[eb + (c0 ^ sw)]       = *(uint4*)&hib[0];
            *(uint4*)&obh[eb + ((c0 + 8) ^ sw)] = *(uint4*)&hib[8];
            *(uint4*)&obl[eb + (c0 ^ sw)]       = *(uint4*)&lob[0];
            *(uint4*)&obl[eb + ((c0 + 8) ^ sw)] = *(uint4*)&lob[8];
        }
        TM_FENCE_BEFORE();
#pragma unroll
        for (int o = 16; o; o >>= 1) dmax = fmaxf(dmax, __shfl_xor_sync(0xffffffffu, dmax, o));
        if (lane == 0) s_red[wid] = dmax;
    }
    __syncthreads();
    if (tid == 0) {
        float v = s_red[0];
#pragma unroll
        for (int w = 1; w < 8; w++) v = fmaxf(v, s_red[w]);
        atomicMax(&g_delta, __float_as_uint(v));
    }
    __syncthreads();
    if (wid == 0) { TM_RELINQ(); TM_DEALLOC(tmem, NT); }

#else
    // ================= fp32 FFMA fallback (baseline compile pass) =================
    float* As = (float*)dynsmem;                  // [16][128]
    float* Bs = (float*)(dynsmem + 16 * 128 * 4); // [16][64]
    __shared__ float red[8];

    const float* __restrict__ curin = (l == 0) ? g_x32 : g_s32[rb ^ 1][l - 1];
    const float* __restrict__ hprev = g_s32[rb][l];
    float* __restrict__ hout        = g_s32[rb ^ 1][l];
    const float* __restrict__ Wp    = &g_Wp[l * KDIM * VDIM];

    int ty = tid >> 4, tx = tid & 15;
    int m0 = blockIdx.x * 128;
    float dmax_all = 0.f;

    for (int vc = 0; vc < 4; vc++) {
        int v0 = blockIdx.y * NT + vc * 64;
        float acc[8][4];
#pragma unroll
        for (int i = 0; i < 8; i++)
#pragma unroll
            for (int j = 0; j < 4; j++) acc[i][j] = 0.f;

        for (int k0 = 0; k0 < KDIM; k0 += 16) {
            const float* Asrc = (k0 < DD) ? curin : hprev;
            int kb2 = k0 & (DD - 1);
            __syncthreads();
#pragma unroll
            for (int s = 0; s < 2; s++) {
                int slot = tid * 2 + s;
                int ml = slot >> 2, k4 = slot & 3;
                float4 va = *(const float4*)&Asrc[(size_t)(m0 + ml) * DD + kb2 + k4 * 4];
                As[(k4 * 4 + 0) * 128 + ml] = va.x; As[(k4 * 4 + 1) * 128 + ml] = va.y;
                As[(k4 * 4 + 2) * 128 + ml] = va.z; As[(k4 * 4 + 3) * 128 + ml] = va.w;
            }
            {
                int kk = tid >> 4, v4 = tid & 15;
                *(float4*)&Bs[kk * 64 + v4 * 4] =
                    *(const float4*)&Wp[(size_t)(k0 + kk) * VDIM + v0 + v4 * 4];
            }
            __syncthreads();
#pragma unroll
            for (int kk = 0; kk < 16; kk++) {
                float4 a0 = *(const float4*)&As[kk * 128 + ty * 8];
                float4 a1 = *(const float4*)&As[kk * 128 + ty * 8 + 4];
                float4 bb = *(const float4*)&Bs[kk * 64 + tx * 4];
                float a[8] = {a0.x, a0.y, a0.z, a0.w, a1.x, a1.y, a1.z, a1.w};
                float b[4] = {bb.x, bb.y, bb.z, bb.w};
#pragma unroll
                for (int i = 0; i < 8; i++)
#pragma unroll
                    for (int j = 0; j < 4; j++) acc[i][j] += a[i] * b[j];
            }
        }

        float bT0 = g_bp[l * VDIM + v0 + tx * 4 + 0];
        float bF0 = g_bp[l * VDIM + v0 + tx * 4 + 1];
        float bT1 = g_bp[l * VDIM + v0 + tx * 4 + 2];
        float bF1 = g_bp[l * VDIM + v0 + tx * 4 + 3];
        int d0 = (v0 >> 1) + tx * 2;
#pragma unroll
        for (int i = 0; i < 8; i++) {
            int m = m0 + ty * 8 + i;
#pragma unroll
            for (int q = 0; q < 2; q++) {
                float hn = epi_update(acc[i][2 * q] + (q ? bT1 : bT0),
                                      acc[i][2 * q + 1] + (q ? bF1 : bF0),
                                      hprev[(size_t)m * DD + d0 + q], dmax_all);
                hout[(size_t)m * DD + d0 + q] = hn;
            }
        }
    }
#pragma unroll
    for (int o = 16; o; o >>= 1) dmax_all = fmaxf(dmax_all, __shfl_xor_sync(0xffffffffu, dmax_all, o));
    if ((tid & 31) == 0) red[tid >> 5] = dmax_all;
    __syncthreads();
    if (tid == 0) {
        float v = red[0];
#pragma unroll
        for (int w = 1; w < 8; w++) v = fmaxf(v, red[w]);
        atomicMax(&g_delta, __float_as_uint(v));
    }
#endif
}

__global__ void check_kernel(int t) {
    if (!g_done) {
        g_last = (t & 1) ^ 1;
        if (__uint_as_float(g_delta) < 1e-3f) { g_done = 1; g_result = t; }
    }
    g_delta = 0u;
}

__global__ void output_kernel(float* __restrict__ out, int n) {
    int idx = blockIdx.x * blockDim.x + threadIdx.x;
    if (idx >= n) return;
    if (idx < M_TOK * DD) out[idx] = g_s32[g_last][NLAYERS - 1][idx];
    else                  out[idx] = (float)g_result;
}

// ---------------------------------------------------------------
extern "C" void kernel_launch(void* const* d_in, const int* in_sizes, int n_in,
                              void* d_out, int out_size) {
    const float* x  = (const float*)d_in[0];
    const float* Ws = (const float*)d_in[1];
    const float* bs = (const float*)d_in[2];
    const float* Wi = (const float*)d_in[3];
    const float* bi = (const float*)d_in[4];
    const float* Wt = (const float*)d_in[5];
    const float* bt = (const float*)d_in[6];

    static int attr_set = 0;
    if (!attr_set) {
        cudaFuncSetAttribute(layer_kernel, cudaFuncAttributeMaxDynamicSharedMemorySize, DYN_SMEM);
        attr_set = 1;
    }

    init_kernel<<<8192, 256>>>();
    xcvt_kernel<<<(M_TOK * DD + 255) / 256, 256>>>(x);
    pack_kernel<<<(NLAYERS * KDIM * VDIM + 255) / 256, 256>>>(Ws, bs, Wi, bi, Wt, bt);

    dim3 grid(M_TOK / MT, VDIM / NT);   // 64 x 2 = 128 CTAs
    for (int t = 0; t < TMAX; t++) {
        for (int l = 0; l < NLAYERS; l++)
            layer_kernel<<<grid, 256, DYN_SMEM>>>(l, t & 1);
        check_kernel<<<1, 1>>>(t);
    }
    output_kernel<<<(out_size + 255) / 256, 256>>>((float*)d_out, out_size);
}

// round 8
// speedup vs baseline: 5.6180x; 1.3233x over previous
#include <cuda_runtime.h>
#include <cuda_bf16.h>
#include <math.h>
#include <stdint.h>

#define M_TOK   8192     // B*S
#define DD      256      // hidden dim
#define KDIM    512      // combined input dim
#define VDIM    512      // virtual output dim (tau/forcing interleaved)
#define NLAYERS 4
#define TMAX    50

#define MT 128           // M tile per CTA
#define NT 256           // N tile per CTA (TMEM D cols)
#define STAGE_BYTES 98304    // Ahi 16K + Alo 16K + Bhi 32K + Blo 32K
#define DYN_SMEM (2*STAGE_BYTES + 1024)   // +1024 for manual alignment

// idesc kind::f16: dtype=F32, atype=btype=BF16, N=256, M=128
#define IDESC 0x8400490u

// Arch gate: tcgen05 only in the sm_103a pass; baseline compute_103 pass
// gets the fp32 FFMA fallback.
#if defined(__CUDA_ARCH__) && (__CUDA_ARCH__ == 1030) && \
    (defined(__CUDA_ARCH_FEAT_SM103_ALL) || defined(__CUDA_ARCH_SPECIFIC__))
#define TC_PATH 1
#else
#define TC_PATH 0
#endif

// ---------------- device globals (allocation-free scratch) ----------------
// bf16 planes stored PRE-SWIZZLED, k-blocked: elem (kb, m, c) at
// (kb*8192 + m)*64 + (c ^ ((m&7)<<3)) — 16 KB contiguous per (kb, 128-row
// tile), byte-identical to the SW128 smem tile image.
__device__ __align__(256) float          g_s32[2][NLAYERS][M_TOK*DD];  // fp32 states
__device__ __align__(256) __nv_bfloat16  g_sbh[2][NLAYERS][M_TOK*DD];  // bf16 hi plane (swizzled)
__device__ __align__(256) __nv_bfloat16  g_sbl[2][NLAYERS][M_TOK*DD];  // bf16 lo plane (swizzled)
__device__ __align__(256) float          g_x32[M_TOK*DD];
__device__ __align__(256) __nv_bfloat16  g_xh[M_TOK*DD];               // swizzled
__device__ __align__(256) __nv_bfloat16  g_xl[M_TOK*DD];               // swizzled
// weights: [l][vt(2)][kb(8)] blocks of 256x64 swizzled = 16384 elems each
__device__ __align__(256) __nv_bfloat16  g_wh[NLAYERS*VDIM*KDIM];
__device__ __align__(256) __nv_bfloat16  g_wl[NLAYERS*VDIM*KDIM];
__device__ __align__(256) float          g_Wp[NLAYERS*KDIM*VDIM];      // fp32 [l][k][v] (fallback)
__device__ float    g_bp[NLAYERS*VDIM];
__device__ int      g_done;
__device__ int      g_result;
__device__ unsigned g_delta;
__device__ int      g_last;
__device__ unsigned g_count;

// ---------------- inline PTX helpers ----------------
__device__ __forceinline__ uint32_t smem_u32(const void* p) {
    uint32_t a;
    asm("{ .reg .u64 t; cvta.to.shared.u64 t, %1; cvt.u32.u64 %0, t; }" : "=r"(a) : "l"(p));
    return a;
}

__device__ __forceinline__ uint64_t make_desc(uint32_t addr) {
    const uint64_t base = (2ULL << 61) | (1ULL << 46) | (64ULL << 32) | (1ULL << 16); // SW128, LBO=1, SBO=64
    return base | (uint64_t)((addr >> 4) & 0x3FFF);
}

#define MBAR_INIT(a, c) asm volatile("mbarrier.init.shared.b64 [%0], %1;" :: "r"(a), "r"(c) : "memory")
#define MBAR_EXPECT_TX(a, b) asm volatile("mbarrier.arrive.expect_tx.shared.b64 _, [%0], %1;" :: "r"(a), "r"(b) : "memory")
#define MBAR_WAIT(a, par) do { \
    uint32_t _m = (a), _p = (par), _d; \
    asm volatile("{\n\t.reg .pred p;\n\tmbarrier.try_wait.parity.acquire.cta.shared::cta.b64 p, [%1], %2;\n\tselp.b32 %0, 1, 0, p;\n\t}" \
        : "=r"(_d) : "r"(_m), "r"(_p) : "memory"); \
    if (!_d) { \
        asm volatile("{\n\t.reg .pred P1;\n\tWL_%=:\n\tmbarrier.try_wait.parity.acquire.cta.shared::cta.b64 P1, [%0], %1, 0x989680;\n\t@P1 bra.uni WD_%=;\n\tbra.uni WL_%=;\n\tWD_%=:\n\t}" \
            :: "r"(_m), "r"(_p) : "memory"); \
    } } while (0)

#define CLUSTER_SYNC() do { \
    asm volatile("barrier.cluster.arrive.aligned;" ::: "memory"); \
    asm volatile("barrier.cluster.wait.aligned;" ::: "memory"); } while (0)

#if TC_PATH
// multicast bulk copy: data + complete_tx delivered to the same smem offset /
// mbarrier offset in every CTA whose bit is set in mask.
#define CP_BULK_MC(dst, src, bytes, mbar, mask) \
    asm volatile("cp.async.bulk.shared::cluster.global.mbarrier::complete_tx::bytes.multicast::cluster [%0], [%1], %2, [%3], %4;" \
        :: "r"(dst), "l"(src), "r"(bytes), "r"(mbar), "h"((uint16_t)(mask)) : "memory")

#define MBAR_ARRIVE_RANK(addr, rank) \
    asm volatile("{\n\t.reg .b32 ra;\n\tmapa.shared::cluster.u32 ra, %0, %1;\n\tmbarrier.arrive.shared::cluster.b64 _, [ra];\n\t}" \
        :: "r"(addr), "r"(rank) : "memory")

#define TM_ALLOC(sa, n)   asm volatile("tcgen05.alloc.cta_group::1.sync.aligned.shared::cta.b32 [%0], %1;" :: "r"(sa), "r"(n) : "memory")
#define TM_DEALLOC(t, n)  asm volatile("tcgen05.dealloc.cta_group::1.sync.aligned.b32 %0, %1;" :: "r"(t), "r"(n))
#define TM_RELINQ()       asm volatile("tcgen05.relinquish_alloc_permit.cta_group::1.sync.aligned;")
#define TM_COMMIT(mb)     asm volatile("tcgen05.commit.cta_group::1.mbarrier::arrive::one.shared::cluster.b64 [%0];" :: "r"(mb) : "memory")
#define TM_WAIT_LD()      asm volatile("tcgen05.wait::ld.sync.aligned;" ::: "memory")
#define TM_FENCE_AFTER()  asm volatile("tcgen05.fence::after_thread_sync;" ::: "memory")
#define TM_FENCE_BEFORE() asm volatile("tcgen05.fence::before_thread_sync;" ::: "memory")

__device__ __forceinline__ void mma_f16_ss(uint32_t d, uint64_t a, uint64_t b, uint32_t idesc, bool en) {
    uint32_t e = en ? 1u : 0u;
    asm volatile(
        "{\n\t.reg .pred p;\n\tsetp.ne.u32 p, %5, 0;\n\t"
        "tcgen05.mma.cta_group::1.kind::f16 [%0], %1, %2, %3, {%4, %4, %4, %4}, p;\n\t}"
        :: "r"(d), "l"(a), "l"(b), "r"(idesc), "r"(0u), "r"(e) : "memory");
}

#define TM_LD_X32(r, ta) \
    asm volatile("tcgen05.ld.sync.aligned.32x32b.x32.b32 " \
        "{%0,%1,%2,%3,%4,%5,%6,%7,%8,%9,%10,%11,%12,%13,%14,%15," \
        "%16,%17,%18,%19,%20,%21,%22,%23,%24,%25,%26,%27,%28,%29,%30,%31}, [%32];" \
        : "=r"((r)[0]),"=r"((r)[1]),"=r"((r)[2]),"=r"((r)[3]),"=r"((r)[4]),"=r"((r)[5]),"=r"((r)[6]),"=r"((r)[7]), \
          "=r"((r)[8]),"=r"((r)[9]),"=r"((r)[10]),"=r"((r)[11]),"=r"((r)[12]),"=r"((r)[13]),"=r"((r)[14]),"=r"((r)[15]), \
          "=r"((r)[16]),"=r"((r)[17]),"=r"((r)[18]),"=r"((r)[19]),"=r"((r)[20]),"=r"((r)[21]),"=r"((r)[22]),"=r"((r)[23]), \
          "=r"((r)[24]),"=r"((r)[25]),"=r"((r)[26]),"=r"((r)[27]),"=r"((r)[28]),"=r"((r)[29]),"=r"((r)[30]),"=r"((r)[31]) \
        : "r"(ta))
#endif // TC_PATH

// ---------------------------------------------------------------
__global__ void init_kernel() {
    size_t idx = (size_t)blockIdx.x * blockDim.x + threadIdx.x;
    float4 z = make_float4(0.f, 0.f, 0.f, 0.f);
    if (idx < (size_t)NLAYERS * M_TOK * DD / 4) ((float4*)&g_s32[0][0][0])[idx] = z;
    if (idx < (size_t)NLAYERS * M_TOK * DD / 8) {
        ((float4*)&g_sbh[0][0][0])[idx] = z;
        ((float4*)&g_sbl[0][0][0])[idx] = z;
    }
    if (idx == 0) { g_done = 0; g_result = TMAX; g_delta = 0u; g_last = 0; g_count = 0u; }
}

__global__ void xcvt_kernel(const float* __restrict__ x) {
    int idx = blockIdx.x * blockDim.x + threadIdx.x;
    if (idx < M_TOK * DD) {
        float v = x[idx];
        g_x32[idx] = v;
        int m = idx >> 8, d = idx & 255;
        int kb = d >> 6, c = d & 63;
        size_t o = ((size_t)kb * 8192 + m) * 64 + (c ^ ((m & 7) << 3));  // swizzled
        __nv_bfloat16 hi = __float2bfloat16(v);
        g_xh[o] = hi;
        g_xl[o] = __float2bfloat16(v - __bfloat162float(hi));
    }
}

__global__ void pack_kernel(const float* __restrict__ Ws, const float* __restrict__ bs,
                            const float* __restrict__ Wi, const float* __restrict__ bi,
                            const float* __restrict__ Wt, const float* __restrict__ bt) {
    int idx = blockIdx.x * blockDim.x + threadIdx.x;
    int total = NLAYERS * KDIM * VDIM;
    if (idx < total) {
        int l = idx / (KDIM * VDIM);
        int rem = idx % (KDIM * VDIM);
        int k = rem / VDIM;
        int v = rem % VDIM;
        int d = v >> 1, half = v & 1;
        float w;
        if (half == 0)      w = Wt[(l * DD + d) * KDIM + k];
        else if (k < DD)    w = Wi[(l * DD + d) * DD + k];
        else                w = Ws[(l * DD + d) * DD + (k - DD)];
        g_Wp[idx] = w;                                    // fp32 [l][k][v] (fallback)
        // bf16 swizzled blocks: [l][vt][kb] of 256x64
        int vt = v >> 8, vl = v & 255, kb = k >> 6, c = k & 63;
        size_t o = (size_t)(((l * 2 + vt) * 8 + kb)) * 16384 + vl * 64 + (c ^ ((vl & 7) << 3));
        __nv_bfloat16 hi = __float2bfloat16(w);
        g_wh[o] = hi;
        g_wl[o] = __float2bfloat16(w - __bfloat162float(hi));
    }
    if (idx < NLAYERS * VDIM) {
        int l = idx / VDIM, v = idx % VDIM, d = v >> 1, half = v & 1;
        g_bp[idx] = half ? (bs[l * DD + d] + bi[l * DD + d]) : bt[l * DD + d];
    }
}

// epilogue scalar: intrinsic transcendentals (inf-safe at saturation)
__device__ __forceinline__ float epi_update(float pt, float pf, float h, float& dmax) {
    float e   = __expf(-pt);                       // sigmoid; pt<<0 -> e=inf -> tau=0
    float tau = __fdividef(1.f, 1.f + e);
    float ax  = fabsf(pf);
    float e2  = __expf(ax + ax);                   // |pf| large -> inf -> th=1
    float th  = 1.f - __fdividef(2.f, e2 + 1.f);
    float forc = copysignf(th, pf);
    float hn = h + 0.05f * (forc - __fdividef(h, tau + 1e-6f));
    hn = fminf(10.f, fmaxf(-10.f, hn));
    dmax = fmaxf(dmax, fabsf(hn - h));
    return hn;
}

// fused convergence check (runs in last CTA of the l==3 kernel)
__device__ __forceinline__ void fused_check(int t) {
    __threadfence();
    unsigned c = atomicAdd(&g_count, 1u);
    if (c == 127u) {
        unsigned dbits = atomicMax(&g_delta, 0u);   // coherent read
        g_count = 0u;
        g_last = (t & 1) ^ 1;
        if (__uint_as_float(dbits) < 1e-3f) { g_done = 1; g_result = t; }
        g_delta = 0u;
    }
}

// One layer-step: GEMM [8192x512]x[512x512]^T + fused epilogue + delta reduce.
// Cluster (2,2): A-planes multicast across the vt pair, B-planes across the m pair.
__global__ __launch_bounds__(256, 1) __cluster_dims__(2, 2, 1)
void layer_kernel(int l, int rb, int t) {
    if (g_done) return;

    extern __shared__ char dynsmem[];
    const int tid = threadIdx.x;

#if TC_PATH
    // ================= tcgen05 split-bf16, multicast-pipelined =================
    __shared__ uint32_t s_tmem;
    __shared__ __align__(8) uint64_t s_mbar[6];   // full[2], mma[2], empty[2]
    __shared__ float s_red[8];

    const int wid = tid >> 5, lane = tid & 31;
    const int m0 = blockIdx.x * MT;
    const int vt = blockIdx.y;           // 0 or 1
    const int v0 = vt * NT;
    const int cx = blockIdx.x & 1;       // cluster coords
    const int cy = blockIdx.y & 1;
    const uint16_t amask = (uint16_t)((1u << cx) | (1u << (cx + 2)));  // same-x pair
    const uint16_t bmask = (uint16_t)(3u << (2 * cy));                 // same-y pair

    const __nv_bfloat16* __restrict__ cin_h = (l == 0) ? g_xh : g_sbh[rb ^ 1][l - 1];
    const __nv_bfloat16* __restrict__ cin_l = (l == 0) ? g_xl : g_sbl[rb ^ 1][l - 1];
    const __nv_bfloat16* __restrict__ hp_h  = g_sbh[rb][l];
    const __nv_bfloat16* __restrict__ hp_l  = g_sbl[rb][l];
    const float* __restrict__ hp32          = g_s32[rb][l];
    float* __restrict__ o32                 = g_s32[rb ^ 1][l];
    __nv_bfloat16* __restrict__ obh         = g_sbh[rb ^ 1][l];
    __nv_bfloat16* __restrict__ obl         = g_sbl[rb ^ 1][l];
    const __nv_bfloat16* __restrict__ wbh   = g_wh + (size_t)((l * 2 + vt) * 8) * 16384;
    const __nv_bfloat16* __restrict__ wbl   = g_wl + (size_t)((l * 2 + vt) * 8) * 16384;

    uint32_t full_mb[2], mma_mb[2], empty_mb[2];
    full_mb[0]  = smem_u32(&s_mbar[0]); full_mb[1]  = smem_u32(&s_mbar[1]);
    mma_mb[0]   = smem_u32(&s_mbar[2]); mma_mb[1]   = smem_u32(&s_mbar[3]);
    empty_mb[0] = smem_u32(&s_mbar[4]); empty_mb[1] = smem_u32(&s_mbar[5]);
    if (tid == 0) {
        MBAR_INIT(full_mb[0], 1); MBAR_INIT(full_mb[1], 1);
        MBAR_INIT(mma_mb[0], 1);  MBAR_INIT(mma_mb[1], 1);
        MBAR_INIT(empty_mb[0], 4); MBAR_INIT(empty_mb[1], 4);   // one arrive per cluster CTA
    }
    if (wid == 0) TM_ALLOC(smem_u32(&s_tmem), NT);
    __syncthreads();
    uint32_t tmem;
    asm volatile("ld.shared.b32 %0, [%1];" : "=r"(tmem) : "r"(smem_u32(&s_tmem)));

    const uint32_t sbase = (smem_u32(dynsmem) + 1023u) & ~1023u;   // SW128 needs 1024-align

    // all peers' mbarriers must be init'd before any multicast targets them
    CLUSTER_SYNC();

    if (tid == 0) {
        // Each CTA issues 2 multicast bulk ops per stage:
        //   A-plane (hi if cy==0 else lo) of its own m-tile  -> vt pair
        //   B-plane (hi if cx==0 else lo) of its own vt      -> m pair
        // and receives the full 96 KB stage (expect_tx local, tx from 4 ops).
        auto issue_loads = [&](int kb, uint32_t stage, uint32_t fmb) {
            MBAR_EXPECT_TX(fmb, (uint32_t)STAGE_BYTES);
            const __nv_bfloat16* ah; const __nv_bfloat16* al; int akb;
            if (kb < 4) { ah = cin_h; al = cin_l; akb = kb; }
            else        { ah = hp_h;  al = hp_l;  akb = kb - 4; }
            const __nv_bfloat16* asrc = (cy ? al : ah) + ((size_t)akb * 8192 + m0) * 64;
            CP_BULK_MC(stage + cy * 16384, asrc, 16384u, fmb, amask);
            const __nv_bfloat16* bsrc = (cx ? wbl : wbh) + (size_t)kb * 16384;
            CP_BULK_MC(stage + 32768 + cx * 32768, bsrc, 32768u, fmb, bmask);
        };

        issue_loads(0, sbase, full_mb[0]);
        issue_loads(1, sbase + STAGE_BYTES, full_mb[1]);

        for (int kb = 0; kb < 8; kb++) {
            const int s = kb & 1, ph = (kb >> 1) & 1;
            const uint32_t stage = sbase + s * STAGE_BYTES;
            MBAR_WAIT(full_mb[s], ph);

            uint64_t dah = make_desc(stage);
            uint64_t dal = make_desc(stage + 16384);
            uint64_t dbh = make_desc(stage + 32768);
            uint64_t dbl = make_desc(stage + 65536);
#pragma unroll
            for (int pass = 0; pass < 3; pass++) {
                uint64_t da = (pass == 2) ? dal : dah;
                uint64_t db = (pass == 1) ? dbl : dbh;
#pragma unroll
                for (int kc = 0; kc < 4; kc++)
                    mma_f16_ss(tmem, da + kc * 2, db + kc * 2, IDESC,
                               !(kb == 0 && pass == 0 && kc == 0));
            }
            TM_COMMIT(mma_mb[s]);

            if (kb < 6) {
                MBAR_WAIT(mma_mb[s], ph);          // own stage-s MMAs done
                // announce to all cluster CTAs that OUR reads of stage s finished
                MBAR_ARRIVE_RANK(empty_mb[s], 0);
                MBAR_ARRIVE_RANK(empty_mb[s], 1);
                MBAR_ARRIVE_RANK(empty_mb[s], 2);
                MBAR_ARRIVE_RANK(empty_mb[s], 3);
                MBAR_WAIT(empty_mb[s], ph);        // all 4 CTAs done with stage s
                issue_loads(kb + 2, stage, full_mb[s]);
            }
        }
        MBAR_WAIT(mma_mb[1], 1);                   // final MMA (kb=7) done
    }
    __syncthreads();
    TM_FENCE_AFTER();

    // -------- fused epilogue: 8 warps; warp w -> rows (w&3)*32, col-half w>>2 --------
    float dmax = 0.f;
    {
        const int m = m0 + (wid & 3) * 32 + lane;
        const int cb0 = (wid >> 2) * 4;
        const float* hp = hp32 + (size_t)m * DD;
        float* orow = o32 + (size_t)m * DD;
        const int sw = (m & 7) << 3;
#pragma unroll
        for (int ci = 0; ci < 4; ci++) {
            const int cb = cb0 + ci;
            uint32_t r[32];
            TM_LD_X32(r, tmem + cb * 32);
            TM_WAIT_LD();
            const int dbase = (v0 >> 1) + cb * 16;
            const float* bp = &g_bp[l * VDIM + v0 + cb * 32];
            __align__(16) float hnv[16];
            __align__(16) __nv_bfloat16 hib[16], lob[16];
#pragma unroll
            for (int j = 0; j < 16; j++) {
                float pt = __uint_as_float(r[2 * j])     + bp[2 * j];
                float pf = __uint_as_float(r[2 * j + 1]) + bp[2 * j + 1];
                float hn = epi_update(pt, pf, hp[dbase + j], dmax);
                hnv[j] = hn;
                __nv_bfloat16 hi = __float2bfloat16(hn);
                hib[j] = hi;
                lob[j] = __float2bfloat16(hn - __bfloat162float(hi));
            }
#pragma unroll
            for (int q = 0; q < 4; q++)
                *(float4*)&orow[dbase + q * 4] = *(float4*)&hnv[q * 4];
            // swizzled k-blocked plane stores (2x16B per plane)
            const int kbd = dbase >> 6, c0 = dbase & 63;
            const size_t eb = ((size_t)kbd * 8192 + m) * 64;
            *(uint4*)&obh[eb + (c0 ^ sw)]       = *(uint4*)&hib[0];
            *(uint4*)&obh[eb + ((c0 + 8) ^ sw)] = *(uint4*)&hib[8];
            *(uint4*)&obl[eb + (c0 ^ sw)]       = *(uint4*)&lob[0];
            *(uint4*)&obl[eb + ((c0 + 8) ^ sw)] = *(uint4*)&lob[8];
        }
        TM_FENCE_BEFORE();
#pragma unroll
        for (int o = 16; o; o >>= 1) dmax = fmaxf(dmax, __shfl_xor_sync(0xffffffffu, dmax, o));
        if (lane == 0) s_red[wid] = dmax;
    }
    __syncthreads();
    if (tid == 0) {
        float v = s_red[0];
#pragma unroll
        for (int w = 1; w < 8; w++) v = fmaxf(v, s_red[w]);
        atomicMax(&g_delta, __float_as_uint(v));
        if (l == 3) fused_check(t);
    }
    __syncthreads();
    if (wid == 0) { TM_RELINQ(); TM_DEALLOC(tmem, NT); }

#else
    // ================= fp32 FFMA fallback (baseline compile pass) =================
    float* As = (float*)dynsmem;                  // [16][128]
    float* Bs = (float*)(dynsmem + 16 * 128 * 4); // [16][64]
    __shared__ float red[8];

    const float* __restrict__ curin = (l == 0) ? g_x32 : g_s32[rb ^ 1][l - 1];
    const float* __restrict__ hprev = g_s32[rb][l];
    float* __restrict__ hout        = g_s32[rb ^ 1][l];
    const float* __restrict__ Wp    = &g_Wp[l * KDIM * VDIM];

    int ty = tid >> 4, tx = tid & 15;
    int m0 = blockIdx.x * 128;
    float dmax_all = 0.f;

    for (int vc = 0; vc < 4; vc++) {
        int v0 = blockIdx.y * NT + vc * 64;
        float acc[8][4];
#pragma unroll
        for (int i = 0; i < 8; i++)
#pragma unroll
            for (int j = 0; j < 4; j++) acc[i][j] = 0.f;

        for (int k0 = 0; k0 < KDIM; k0 += 16) {
            const float* Asrc = (k0 < DD) ? curin : hprev;
            int kb2 = k0 & (DD - 1);
            __syncthreads();
#pragma unroll
            for (int s = 0; s < 2; s++) {
                int slot = tid * 2 + s;
                int ml = slot >> 2, k4 = slot & 3;
                float4 va = *(const float4*)&Asrc[(size_t)(m0 + ml) * DD + kb2 + k4 * 4];
                As[(k4 * 4 + 0) * 128 + ml] = va.x; As[(k4 * 4 + 1) * 128 + ml] = va.y;
                As[(k4 * 4 + 2) * 128 + ml] = va.z; As[(k4 * 4 + 3) * 128 + ml] = va.w;
            }
            {
                int kk = tid >> 4, v4 = tid & 15;
                *(float4*)&Bs[kk * 64 + v4 * 4] =
                    *(const float4*)&Wp[(size_t)(k0 + kk) * VDIM + v0 + v4 * 4];
            }
            __syncthreads();
#pragma unroll
            for (int kk = 0; kk < 16; kk++) {
                float4 a0 = *(const float4*)&As[kk * 128 + ty * 8];
                float4 a1 = *(const float4*)&As[kk * 128 + ty * 8 + 4];
                float4 bb = *(const float4*)&Bs[kk * 64 + tx * 4];
                float a[8] = {a0.x, a0.y, a0.z, a0.w, a1.x, a1.y, a1.z, a1.w};
                float b[4] = {bb.x, bb.y, bb.z, bb.w};
#pragma unroll
                for (int i = 0; i < 8; i++)
#pragma unroll
                    for (int j = 0; j < 4; j++) acc[i][j] += a[i] * b[j];
            }
        }

        float bT0 = g_bp[l * VDIM + v0 + tx * 4 + 0];
        float bF0 = g_bp[l * VDIM + v0 + tx * 4 + 1];
        float bT1 = g_bp[l * VDIM + v0 + tx * 4 + 2];
        float bF1 = g_bp[l * VDIM + v0 + tx * 4 + 3];
        int d0 = (v0 >> 1) + tx * 2;
#pragma unroll
        for (int i = 0; i < 8; i++) {
            int m = m0 + ty * 8 + i;
#pragma unroll
            for (int q = 0; q < 2; q++) {
                float hn = epi_update(acc[i][2 * q] + (q ? bT1 : bT0),
                                      acc[i][2 * q + 1] + (q ? bF1 : bF0),
                                      hprev[(size_t)m * DD + d0 + q], dmax_all);
                hout[(size_t)m * DD + d0 + q] = hn;
            }
        }
    }
#pragma unroll
    for (int o = 16; o; o >>= 1) dmax_all = fmaxf(dmax_all, __shfl_xor_sync(0xffffffffu, dmax_all, o));
    if ((tid & 31) == 0) red[tid >> 5] = dmax_all;
    __syncthreads();
    if (tid == 0) {
        float v = red[0];
#pragma unroll
        for (int w = 1; w < 8; w++) v = fmaxf(v, red[w]);
        atomicMax(&g_delta, __float_as_uint(v));
        if (l == 3) fused_check(t);
    }
#endif
}

__global__ void output_kernel(float* __restrict__ out, int n) {
    int idx = blockIdx.x * blockDim.x + threadIdx.x;
    if (idx >= n) return;
    if (idx < M_TOK * DD) out[idx] = g_s32[g_last][NLAYERS - 1][idx];
    else                  out[idx] = (float)g_result;
}

// ---------------------------------------------------------------
extern "C" void kernel_launch(void* const* d_in, const int* in_sizes, int n_in,
                              void* d_out, int out_size) {
    const float* x  = (const float*)d_in[0];
    const float* Ws = (const float*)d_in[1];
    const float* bs = (const float*)d_in[2];
    const float* Wi = (const float*)d_in[3];
    const float* bi = (const float*)d_in[4];
    const float* Wt = (const float*)d_in[5];
    const float* bt = (const float*)d_in[6];

    static int attr_set = 0;
    if (!attr_set) {
        cudaFuncSetAttribute(layer_kernel, cudaFuncAttributeMaxDynamicSharedMemorySize, DYN_SMEM);
        attr_set = 1;
    }

    init_kernel<<<8192, 256>>>();
    xcvt_kernel<<<(M_TOK * DD + 255) / 256, 256>>>(x);
    pack_kernel<<<(NLAYERS * KDIM * VDIM + 255) / 256, 256>>>(Ws, bs, Wi, bi, Wt, bt);

    dim3 grid(M_TOK / MT, VDIM / NT);   // 64 x 2 = 128 CTAs, clusters of (2,2)
    for (int t = 0; t < TMAX; t++) {
        for (int l = 0; l < NLAYERS; l++)
            layer_kernel<<<grid, 256, DYN_SMEM>>>(l, t & 1, t);
    }
    output_kernel<<<(out_size + 255) / 256, 256>>>((float*)d_out, out_size);
}